// round 14
// baseline (speedup 1.0000x reference)
#include <cuda_runtime.h>
#include <cuda_bf16.h>
#include <cstdint>

// Shapes fixed by the dataset
#define BB 8
#define EE 256
#define LL 4096
#define SS 256          // top_k
#define HH 8
#define SCALEF 0.17677669529663687f   // 1/sqrt(32)

typedef unsigned long long ull;

// ---------------- device scratch ----------------
__device__ float g_nQs[BB * EE * SS];          // negated gathered queries [b][e][s]
__device__ float g_mind[BB * LL];              // min L1 distance per key pos
__device__ ull   g_cand[BB * 2048];            // per-chunk top-256 candidates
__device__ int   g_sel[BB * SS];               // selected indices
__device__ float g_WT[4 * EE * EE];            // transposed weights [m][ei][eo] (kvproj)
__device__ __nv_bfloat16 g_Wqh[EE * EE];       // Wq bf16 hi [eo][ei]
__device__ __nv_bfloat16 g_Wql[EE * EE];       // Wq bf16 lo
__device__ __nv_bfloat16 g_Woh[EE * EE];       // Wo bf16 hi [eo][ei]
__device__ __nv_bfloat16 g_Wol[EE * EE];       // Wo bf16 lo
__device__ __nv_bfloat16 g_qbh[(size_t)BB * EE * LL];  // projected Q bf16 hi [b][e][l]
__device__ __nv_bfloat16 g_qbl[(size_t)BB * EE * LL];  // projected Q bf16 lo
__device__ __nv_bfloat16 g_kbh[BB * SS * EE];  // projected K bf16 hi [b][j][e]
__device__ __nv_bfloat16 g_kbl[BB * SS * EE];
__device__ __nv_bfloat16 g_vbh[BB * SS * EE];  // projected V bf16 hi [b][j][e]
__device__ __nv_bfloat16 g_vbl[BB * SS * EE];
__device__ __nv_bfloat16 g_obh[(size_t)BB * EE * LL];  // attn out bf16 hi [b][e][l]
__device__ __nv_bfloat16 g_obl[(size_t)BB * EE * LL];

// ---------------- packed f32x2 helpers ----------------
__device__ __forceinline__ ull pk2(float lo, float hi) {
    ull r; asm("mov.b64 %0, {%1,%2};" : "=l"(r) : "f"(lo), "f"(hi)); return r;
}
__device__ __forceinline__ ull fadd2(ull a, ull b) {
    ull d; asm("add.rn.f32x2 %0, %1, %2;" : "=l"(d) : "l"(a), "l"(b)); return d;
}
__device__ __forceinline__ float2 upk2(ull v) {
    float2 r; asm("mov.b64 {%0,%1}, %2;" : "=f"(r.x), "=f"(r.y) : "l"(v)); return r;
}

// ---------------- warp MMA helpers ----------------
__device__ __forceinline__ uint32_t smem_u32(const void* p) {
    uint32_t a;
    asm("{ .reg .u64 t; cvta.to.shared.u64 t, %1; cvt.u32.u64 %0, t; }" : "=r"(a) : "l"(p));
    return a;
}
__device__ __forceinline__ uint32_t pkbf2(float lo, float hi) {
    uint32_t r; asm("cvt.rn.bf16x2.f32 %0, %1, %2;" : "=r"(r) : "f"(hi), "f"(lo)); return r;
}
__device__ __forceinline__ float lo16f(uint32_t u) { return __uint_as_float(u << 16); }
__device__ __forceinline__ float hi16f(uint32_t u) { return __uint_as_float(u & 0xFFFF0000u); }

__device__ __forceinline__ void ldmx4(uint32_t& r0, uint32_t& r1, uint32_t& r2, uint32_t& r3,
                                      uint32_t addr) {
    asm volatile("ldmatrix.sync.aligned.m8n8.x4.shared.b16 {%0,%1,%2,%3}, [%4];"
                 : "=r"(r0), "=r"(r1), "=r"(r2), "=r"(r3) : "r"(addr));
}
__device__ __forceinline__ void ldmx4t(uint32_t& r0, uint32_t& r1, uint32_t& r2, uint32_t& r3,
                                       uint32_t addr) {
    asm volatile("ldmatrix.sync.aligned.m8n8.x4.trans.shared.b16 {%0,%1,%2,%3}, [%4];"
                 : "=r"(r0), "=r"(r1), "=r"(r2), "=r"(r3) : "r"(addr));
}
__device__ __forceinline__ void mma16816(float* d, uint32_t a0, uint32_t a1, uint32_t a2,
                                         uint32_t a3, uint32_t b0, uint32_t b1) {
    asm volatile("mma.sync.aligned.m16n8k16.row.col.f32.bf16.bf16.f32 "
                 "{%0,%1,%2,%3}, {%4,%5,%6,%7}, {%8,%9}, {%0,%1,%2,%3};"
                 : "+f"(d[0]), "+f"(d[1]), "+f"(d[2]), "+f"(d[3])
                 : "r"(a0), "r"(a1), "r"(a2), "r"(a3), "r"(b0), "r"(b1));
}

// ============ kernel 0: weight prep ============
__global__ __launch_bounds__(256) void k_wt(const float* __restrict__ Wi,
                                            const float* __restrict__ Wo) {
    int lin = blockIdx.x * 256 + threadIdx.x;
    int m = lin >> 16;
    int r = lin & 0xFFFF;
    int ei = r >> 8, eo = r & 255;
    float v = (m < 3) ? Wi[(m * EE + eo) * EE + ei] : Wo[eo * EE + ei];
    g_WT[lin] = v;
    if (m == 0) {
        __nv_bfloat16 hi = __float2bfloat16(v);
        g_Wqh[eo * EE + ei] = hi;
        g_Wql[eo * EE + ei] = __float2bfloat16(v - __bfloat162float(hi));
    } else if (m == 3) {
        __nv_bfloat16 hi = __float2bfloat16(v);
        g_Woh[eo * EE + ei] = hi;
        g_Wol[eo * EE + ei] = __float2bfloat16(v - __bfloat162float(hi));
    }
}

// ============ kernel 1: gather negated subset queries ============
__global__ __launch_bounds__(256) void k_gatherQ(const float* __restrict__ q,
                                                 const int* __restrict__ rind) {
    __shared__ int sidx[SS];
    int b = blockIdx.y, t = threadIdx.x;
    sidx[t] = rind[b * SS + t];
    __syncthreads();
    int e0 = blockIdx.x * 32;
    const float* qb = q + (size_t)b * EE * LL;
    int idx = sidx[t];
    float* dst = g_nQs + ((size_t)b * EE + e0) * SS + t;
    const float* srcp = qb + (size_t)e0 * LL + idx;
#pragma unroll 8
    for (int e = 0; e < 32; e++) dst[e * SS] = -srcp[(size_t)e * LL];
}

// ============ kernel 2: min-over-subset L1 distances (per half) ============
__global__ __launch_bounds__(256, 4) void k_dist(const float* __restrict__ keys, int bbase) {
    __shared__ float Kt[16 * 32];
    __shared__ float Qs[16 * SS];
    int t = threadIdx.x, tx = t & 15, ty = t >> 4;
    int b = bbase + blockIdx.y, lb = blockIdx.x * 32;
    const float* kb = keys + (size_t)b * EE * LL;
    const float* qb = g_nQs + (size_t)b * EE * SS;

    ull acc[2][8];
#pragma unroll
    for (int i = 0; i < 2; i++)
#pragma unroll
        for (int p = 0; p < 8; p++) acc[i][p] = 0ull;

    for (int e0 = 0; e0 < EE; e0 += 16) {
        {
            int r = t >> 4, c2 = (t & 15) * 2;
            *(float2*)&Kt[r * 32 + c2] = *(const float2*)&kb[(size_t)(e0 + r) * LL + lb + c2];
        }
#pragma unroll
        for (int v = 0; v < 4; v++) {
            int lin4 = v * 256 + t;
            int r = lin4 >> 6, c4 = (lin4 & 63) * 4;
            *(float4*)&Qs[r * SS + c4] = *(const float4*)&qb[(size_t)(e0 + r) * SS + c4];
        }
        __syncthreads();
#pragma unroll
        for (int ec = 0; ec < 16; ec++) {
            float kv0 = Kt[ec * 32 + ty * 2];
            float kv1 = Kt[ec * 32 + ty * 2 + 1];
            ull kk0 = pk2(kv0, kv0);
            ull kk1 = pk2(kv1, kv1);
            const ull* qp = (const ull*)&Qs[ec * SS];
#pragma unroll
            for (int p = 0; p < 8; p++) {
                ull q2 = qp[tx + p * 16];
                ull d0 = fadd2(kk0, q2);
                d0 &= 0x7FFFFFFF7FFFFFFFULL;
                acc[0][p] = fadd2(acc[0][p], d0);
                ull d1 = fadd2(kk1, q2);
                d1 &= 0x7FFFFFFF7FFFFFFFULL;
                acc[1][p] = fadd2(acc[1][p], d1);
            }
        }
        __syncthreads();
    }
#pragma unroll
    for (int i = 0; i < 2; i++) {
        float m = 3.0e38f;
#pragma unroll
        for (int p = 0; p < 8; p++) {
            float2 f = upk2(acc[i][p]);
            m = fminf(m, fminf(f.x, f.y));
        }
#pragma unroll
        for (int o = 8; o >= 1; o >>= 1)
            m = fminf(m, __shfl_xor_sync(0xffffffffu, m, o));
        if (tx == 0) g_mind[b * LL + lb + ty * 2 + i] = m;
    }
}

// ============ kernel 3a: per-chunk bitonic 512 -> keep 256 smallest ============
__global__ __launch_bounds__(512) void k_topk1(int bbase) {
    __shared__ ull keyv[512];
    int t = threadIdx.x, chunk = blockIdx.x, b = bbase + blockIdx.y;
    int base = chunk * 512;
    {
        unsigned int bits = __float_as_uint(g_mind[b * LL + base + t]);
        keyv[t] = ((ull)bits << 32) | (unsigned int)(base + t);
    }
    __syncthreads();
    for (int k = 2; k <= 512; k <<= 1) {
        for (int j = k >> 1; j > 0; j >>= 1) {
            int ixj = t ^ j;
            if (ixj > t) {
                ull a = keyv[t], c = keyv[ixj];
                bool up = ((t & k) == 0);
                if ((a > c) == up) { keyv[t] = c; keyv[ixj] = a; }
            }
            __syncthreads();
        }
    }
    if (t < 256) g_cand[b * 2048 + chunk * 256 + t] = keyv[t];
}

// ============ kernel 3b: merge 8x256 candidates -> 256 smallest ============
__global__ __launch_bounds__(1024) void k_topk2(int bbase) {
    __shared__ ull keyv[2048];
    int t = threadIdx.x, b = bbase + blockIdx.x;
    keyv[t] = g_cand[b * 2048 + t];
    keyv[t + 1024] = g_cand[b * 2048 + t + 1024];
    __syncthreads();
    for (int k = 2; k <= 2048; k <<= 1) {
        for (int j = k >> 1; j > 0; j >>= 1) {
            for (int i = t; i < 2048; i += 1024) {
                int ixj = i ^ j;
                if (ixj > i) {
                    ull a = keyv[i], c = keyv[ixj];
                    bool up = ((i & k) == 0);
                    if ((a > c) == up) { keyv[i] = c; keyv[ixj] = a; }
                }
            }
            __syncthreads();
        }
    }
    if (t < SS) g_sel[b * SS + t] = (int)(keyv[t] & 0xFFFFFFFFULL);
}

// ============ kernel 4: gather selected K/V, project, emit bf16 hi/lo [b][j][e] ============
#define KV_SMEM ((64 * 264 + 16 * 128) * 4)
__global__ __launch_bounds__(256) void k_kvproj(const float* __restrict__ keys,
                                                const float* __restrict__ values,
                                                const float* __restrict__ bias_in, int bbase) {
    extern __shared__ float sm[];
    float* skv = sm;
    float* Wt  = sm + 64 * 264;
    __shared__ int sidx[64];
    int t = threadIdx.x, b = bbase + blockIdx.y, jb = blockIdx.x * 64;
    int zc = blockIdx.z, ph = zc >> 1, half = zc & 1;
    if (t < 64) sidx[t] = g_sel[b * SS + jb + t];
    __syncthreads();
    int txE = t & 15, tyJ = t >> 4;

    const float* src = (ph ? values : keys) + (size_t)b * EE * LL;
#pragma unroll 8
    for (int j = 0; j < 64; j++)
        skv[j * 264 + t] = src[(size_t)t * LL + sidx[j]];
    __syncthreads();

    const float* WTm = g_WT + (size_t)(ph + 1) * EE * EE + half * 128;
    float acc[4][8];
#pragma unroll
    for (int i = 0; i < 4; i++)
#pragma unroll
        for (int c = 0; c < 8; c++) acc[i][c] = 0.f;

    for (int ei0 = 0; ei0 < EE; ei0 += 16) {
#pragma unroll
        for (int v = 0; v < 2; v++) {
            int lin4 = v * 256 + t;
            int r = lin4 >> 5, c4 = (lin4 & 31) * 4;
            *(float4*)&Wt[r * 128 + c4] = *(const float4*)&WTm[(size_t)(ei0 + r) * EE + c4];
        }
        __syncthreads();
#pragma unroll
        for (int ec = 0; ec < 16; ec++) {
            float a[4];
#pragma unroll
            for (int i = 0; i < 4; i++) a[i] = skv[(tyJ * 4 + i) * 264 + ei0 + ec];
#pragma unroll
            for (int c = 0; c < 8; c++) {
                float w = Wt[ec * 128 + c * 16 + txE];
#pragma unroll
                for (int i = 0; i < 4; i++) acc[i][c] += a[i] * w;
            }
        }
        __syncthreads();
    }
    __nv_bfloat16* dh = ph ? g_vbh : g_kbh;
    __nv_bfloat16* dl = ph ? g_vbl : g_kbl;
    const float* bp = bias_in + (ph ? 2 * EE : EE) + half * 128;
#pragma unroll
    for (int c = 0; c < 8; c++) {
        int eo = c * 16 + txE;
        float bb = bp[eo];
#pragma unroll
        for (int i = 0; i < 4; i++) {
            float x = acc[i][c] + bb;
            __nv_bfloat16 hi = __float2bfloat16(x);
            size_t o = ((size_t)b * SS + jb + tyJ * 4 + i) * EE + half * 128 + eo;
            dh[o] = hi;
            dl[o] = __float2bfloat16(x - __bfloat162float(hi));
        }
    }
}

// ============ kernel 5: HMMA GEMM  C[eo][l] = W[eo][ei] @ X[ei][l] ============
#define WHI_OFF 0
#define WLO_OFF 18432
#define BHI_OFF 36864
#define BLO_OFF 54272
#define GEMM_SMEM 71680
#define WP 72
#define BP 136

__global__ __launch_bounds__(256, 2) void k_gemm(const float* __restrict__ Bext,
                                                 float* __restrict__ OutExt,
                                                 const float* __restrict__ bias,
                                                 int which, float scale, int bzbase) {
    extern __shared__ char smc[];
    uint32_t sb = smem_u32(smc);
    __nv_bfloat16* Ws_hi = (__nv_bfloat16*)(smc + WHI_OFF);
    __nv_bfloat16* Ws_lo = (__nv_bfloat16*)(smc + WLO_OFF);
    __nv_bfloat16* Bs_hi = (__nv_bfloat16*)(smc + BHI_OFF);
    __nv_bfloat16* Bs_lo = (__nv_bfloat16*)(smc + BLO_OFF);

    int t = threadIdx.x, w = t >> 5, lane = t & 31;
    int lb = blockIdx.x * 128, eo0 = blockIdx.y * 128, b = bzbase + blockIdx.z;

    const __nv_bfloat16* Whi = which ? g_Woh : g_Wqh;
    const __nv_bfloat16* Wlo = which ? g_Wol : g_Wql;

    float o[16][4];
#pragma unroll
    for (int j = 0; j < 16; j++)
#pragma unroll
        for (int i = 0; i < 4; i++) o[j][i] = 0.f;

    for (int ei0 = 0; ei0 < EE; ei0 += 64) {
        for (int idx = t; idx < 2048; idx += 256) {
            int c4 = (idx & 15) * 4, r = idx >> 4;
            size_t g = (size_t)(eo0 + r) * EE + ei0 + c4;
            *(ull*)&Ws_hi[r * WP + c4] = *(const ull*)&Whi[g];
            *(ull*)&Ws_lo[r * WP + c4] = *(const ull*)&Wlo[g];
        }
        if (which == 0) {
            for (int idx = t; idx < 2048; idx += 256) {
                int l4 = (idx & 31) * 4, e = idx >> 5;
                float4 x = *(const float4*)&Bext[((size_t)b * EE + ei0 + e) * LL + lb + l4];
                uint32_t uh0 = pkbf2(x.x, x.y), uh1 = pkbf2(x.z, x.w);
                uint32_t ul0 = pkbf2(x.x - lo16f(uh0), x.y - hi16f(uh0));
                uint32_t ul1 = pkbf2(x.z - lo16f(uh1), x.w - hi16f(uh1));
                *(ull*)&Bs_hi[e * BP + l4] = (ull)uh0 | ((ull)uh1 << 32);
                *(ull*)&Bs_lo[e * BP + l4] = (ull)ul0 | ((ull)ul1 << 32);
            }
        } else {
            for (int idx = t; idx < 2048; idx += 256) {
                int l4 = (idx & 31) * 4, e = idx >> 5;
                size_t g = ((size_t)b * EE + ei0 + e) * LL + lb + l4;
                *(ull*)&Bs_hi[e * BP + l4] = *(const ull*)&g_obh[g];
                *(ull*)&Bs_lo[e * BP + l4] = *(const ull*)&g_obl[g];
            }
        }
        __syncthreads();

        int arow = w * 16 + (lane & 7) + ((lane >> 3) & 1) * 8;
        int brow = (lane & 7) + ((lane >> 3) & 1) * 8;
        int bcol = (lane >> 4) * 8;
#pragma unroll
        for (int ks = 0; ks < 4; ks++) {
            int acol = ks * 16 + (lane >> 4) * 8;
            uint32_t ah0, ah1, ah2, ah3, al0, al1, al2, al3;
            ldmx4(ah0, ah1, ah2, ah3, sb + WHI_OFF + (arow * WP + acol) * 2);
            ldmx4(al0, al1, al2, al3, sb + WLO_OFF + (arow * WP + acol) * 2);
            uint32_t roff = ((ks * 16 + brow) * BP + bcol) * 2;
#pragma unroll
            for (int nt = 0; nt < 8; nt++) {
                uint32_t coff = roff + nt * 32;
                uint32_t bh0, bh1, bh2, bh3, bl0, bl1, bl2, bl3;
                ldmx4t(bh0, bh1, bh2, bh3, sb + BHI_OFF + coff);
                ldmx4t(bl0, bl1, bl2, bl3, sb + BLO_OFF + coff);
                mma16816(o[nt * 2],     ah0, ah1, ah2, ah3, bh0, bh1);
                mma16816(o[nt * 2 + 1], ah0, ah1, ah2, ah3, bh2, bh3);
                mma16816(o[nt * 2],     ah0, ah1, ah2, ah3, bl0, bl1);
                mma16816(o[nt * 2 + 1], ah0, ah1, ah2, ah3, bl2, bl3);
                mma16816(o[nt * 2],     al0, al1, al2, al3, bh0, bh1);
                mma16816(o[nt * 2 + 1], al0, al1, al2, al3, bh2, bh3);
            }
        }
        __syncthreads();
    }

    int r0 = eo0 + w * 16 + (lane >> 2);
    float b0v = bias[r0], b1v = bias[r0 + 8];
    size_t base0 = ((size_t)b * EE + r0) * LL + lb;
    size_t base1 = base0 + 8 * LL;
    if (which == 1) {
#pragma unroll
        for (int j = 0; j < 16; j++) {
            int lc = j * 8 + (lane & 3) * 2;
            *(float2*)&OutExt[base0 + lc] = make_float2(o[j][0] + b0v, o[j][1] + b0v);
            *(float2*)&OutExt[base1 + lc] = make_float2(o[j][2] + b1v, o[j][3] + b1v);
        }
    } else {
#pragma unroll
        for (int j = 0; j < 16; j++) {
            int lc = j * 8 + (lane & 3) * 2;
            float x0 = (o[j][0] + b0v) * scale, x1 = (o[j][1] + b0v) * scale;
            float x2 = (o[j][2] + b1v) * scale, x3 = (o[j][3] + b1v) * scale;
            uint32_t h0 = pkbf2(x0, x1);
            uint32_t l0 = pkbf2(x0 - lo16f(h0), x1 - hi16f(h0));
            uint32_t h1 = pkbf2(x2, x3);
            uint32_t l1 = pkbf2(x2 - lo16f(h1), x3 - hi16f(h1));
            *(uint32_t*)&g_qbh[base0 + lc] = h0;
            *(uint32_t*)&g_qbl[base0 + lc] = l0;
            *(uint32_t*)&g_qbh[base1 + lc] = h1;
            *(uint32_t*)&g_qbl[base1 + lc] = l1;
        }
    }
}

// ============ kernel 6: attention via warp MMA (bf16 hi/lo, pre-converted) ============
#define PITCH 40
#define QHI 0
#define QLO 10240
#define KHI 20480
#define KLO 40960
#define VHI 61440
#define VLO 81920
#define ATTN_SMEM_B 102400

__global__ __launch_bounds__(256, 1) void k_attn_mma(int bbase) {
    extern __shared__ char smc[];
    int t = threadIdx.x, w = t >> 5, lane = t & 31;
    int b = bbase + blockIdx.z, h = blockIdx.y, lb = blockIdx.x * 128;
    uint32_t sb = smem_u32(smc);

    for (int idx = t; idx < 2048; idx += 256) {
        int d = idx >> 6, lp = idx & 63;
        int l = lp * 2;
        size_t g = ((size_t)b * EE + h * 32 + d) * LL + lb + l;
        uint32_t uh = *(const uint32_t*)&g_qbh[g];
        uint32_t ul = *(const uint32_t*)&g_qbl[g];
        *(uint16_t*)(smc + QHI + (l * PITCH + d) * 2) = (uint16_t)uh;
        *(uint16_t*)(smc + QHI + ((l + 1) * PITCH + d) * 2) = (uint16_t)(uh >> 16);
        *(uint16_t*)(smc + QLO + (l * PITCH + d) * 2) = (uint16_t)ul;
        *(uint16_t*)(smc + QLO + ((l + 1) * PITCH + d) * 2) = (uint16_t)(ul >> 16);
    }
    for (int idx = t; idx < 2048; idx += 256) {
        int j = idx >> 3, d4 = (idx & 7) * 4;
        size_t g = ((size_t)b * SS + j) * EE + h * 32 + d4;
        *(ull*)(smc + KHI + (j * PITCH + d4) * 2) = *(const ull*)&g_kbh[g];
        *(ull*)(smc + KLO + (j * PITCH + d4) * 2) = *(const ull*)&g_kbl[g];
        *(ull*)(smc + VHI + (j * PITCH + d4) * 2) = *(const ull*)&g_vbh[g];
        *(ull*)(smc + VLO + (j * PITCH + d4) * 2) = *(const ull*)&g_vbl[g];
    }
    __syncthreads();

    int m0 = w * 16;

    float sc[32][4];
#pragma unroll
    for (int nt = 0; nt < 32; nt++)
#pragma unroll
        for (int i = 0; i < 4; i++) sc[nt][i] = 0.f;

    const uint32_t qb2[2] = { sb + QHI, sb + QLO };
    const uint32_t kb2[2] = { sb + KHI, sb + KLO };
    const int TERM_A[3] = { 0, 0, 1 };
    const int TERM_B[3] = { 0, 1, 0 };
#pragma unroll
    for (int tm = 0; tm < 3; tm++) {
        uint32_t qb = qb2[TERM_A[tm]], kb = kb2[TERM_B[tm]];
#pragma unroll
        for (int kd = 0; kd < 2; kd++) {
            int arow = m0 + (lane & 7) + ((lane >> 3) & 1) * 8;
            int acol = kd * 16 + (lane >> 4) * 8;
            uint32_t a0, a1, a2, a3;
            ldmx4(a0, a1, a2, a3, qb + (arow * PITCH + acol) * 2);
            int brow = (lane & 7) + ((lane >> 4) & 1) * 8;
            int bcol = kd * 16 + ((lane >> 3) & 1) * 8;
#pragma unroll
            for (int jp = 0; jp < 16; jp++) {
                uint32_t b0, b1, b2, b3;
                ldmx4(b0, b1, b2, b3, kb + ((jp * 16 + brow) * PITCH + bcol) * 2);
                mma16816(sc[jp * 2],     a0, a1, a2, a3, b0, b1);
                mma16816(sc[jp * 2 + 1], a0, a1, a2, a3, b2, b3);
            }
        }
    }

    float mx0 = -3.0e38f, mx1 = -3.0e38f;
#pragma unroll
    for (int nt = 0; nt < 32; nt++) {
        mx0 = fmaxf(mx0, fmaxf(sc[nt][0], sc[nt][1]));
        mx1 = fmaxf(mx1, fmaxf(sc[nt][2], sc[nt][3]));
    }
    mx0 = fmaxf(mx0, __shfl_xor_sync(0xffffffffu, mx0, 1));
    mx0 = fmaxf(mx0, __shfl_xor_sync(0xffffffffu, mx0, 2));
    mx1 = fmaxf(mx1, __shfl_xor_sync(0xffffffffu, mx1, 1));
    mx1 = fmaxf(mx1, __shfl_xor_sync(0xffffffffu, mx1, 2));
    float s0 = 0.f, s1 = 0.f;
#pragma unroll
    for (int nt = 0; nt < 32; nt++) {
        sc[nt][0] = __expf(sc[nt][0] - mx0); s0 += sc[nt][0];
        sc[nt][1] = __expf(sc[nt][1] - mx0); s0 += sc[nt][1];
        sc[nt][2] = __expf(sc[nt][2] - mx1); s1 += sc[nt][2];
        sc[nt][3] = __expf(sc[nt][3] - mx1); s1 += sc[nt][3];
    }
    s0 += __shfl_xor_sync(0xffffffffu, s0, 1);
    s0 += __shfl_xor_sync(0xffffffffu, s0, 2);
    s1 += __shfl_xor_sync(0xffffffffu, s1, 1);
    s1 += __shfl_xor_sync(0xffffffffu, s1, 2);
    float ri0 = 1.0f / s0, ri1 = 1.0f / s1;
#pragma unroll
    for (int nt = 0; nt < 32; nt++) {
        sc[nt][0] *= ri0; sc[nt][1] *= ri0;
        sc[nt][2] *= ri1; sc[nt][3] *= ri1;
    }

    float o[4][4];
#pragma unroll
    for (int nt = 0; nt < 4; nt++)
#pragma unroll
        for (int i = 0; i < 4; i++) o[nt][i] = 0.f;

    int vrow = (lane & 7) + ((lane >> 3) & 1) * 8;
    int vcolsel = (lane >> 4) * 8;
#pragma unroll
    for (int kt = 0; kt < 16; kt++) {
        uint32_t ah0 = pkbf2(sc[2 * kt][0], sc[2 * kt][1]);
        uint32_t ah1 = pkbf2(sc[2 * kt][2], sc[2 * kt][3]);
        uint32_t ah2 = pkbf2(sc[2 * kt + 1][0], sc[2 * kt + 1][1]);
        uint32_t ah3 = pkbf2(sc[2 * kt + 1][2], sc[2 * kt + 1][3]);
        uint32_t al0 = pkbf2(sc[2 * kt][0] - lo16f(ah0), sc[2 * kt][1] - hi16f(ah0));
        uint32_t al1 = pkbf2(sc[2 * kt][2] - lo16f(ah1), sc[2 * kt][3] - hi16f(ah1));
        uint32_t al2 = pkbf2(sc[2 * kt + 1][0] - lo16f(ah2), sc[2 * kt + 1][1] - hi16f(ah2));
        uint32_t al3 = pkbf2(sc[2 * kt + 1][2] - lo16f(ah3), sc[2 * kt + 1][3] - hi16f(ah3));
        uint32_t rbase = ((kt * 16 + vrow) * PITCH) * 2;
#pragma unroll
        for (int np = 0; np < 2; np++) {
            uint32_t off = rbase + (np * 16 + vcolsel) * 2;
            uint32_t h0, h1, h2, h3, l0, l1, l2, l3;
            ldmx4t(h0, h1, h2, h3, sb + VHI + off);
            ldmx4t(l0, l1, l2, l3, sb + VLO + off);
            mma16816(o[np * 2],     ah0, ah1, ah2, ah3, h0, h1);
            mma16816(o[np * 2 + 1], ah0, ah1, ah2, ah3, h2, h3);
            mma16816(o[np * 2],     ah0, ah1, ah2, ah3, l0, l1);
            mma16816(o[np * 2 + 1], ah0, ah1, ah2, ah3, l2, l3);
            mma16816(o[np * 2],     al0, al1, al2, al3, h0, h1);
            mma16816(o[np * 2 + 1], al0, al1, al2, al3, h2, h3);
        }
    }

    int rlo = m0 + (lane >> 2);
#pragma unroll
    for (int nt = 0; nt < 4; nt++) {
        int e = h * 32 + nt * 8 + (lane & 3) * 2;
        size_t base = ((size_t)b * EE + e) * LL + lb;
        float x0 = o[nt][0], x1 = o[nt][1], x2 = o[nt][2], x3 = o[nt][3];
        __nv_bfloat16 h0 = __float2bfloat16(x0);
        __nv_bfloat16 h1 = __float2bfloat16(x1);
        __nv_bfloat16 h2 = __float2bfloat16(x2);
        __nv_bfloat16 h3 = __float2bfloat16(x3);
        g_obh[base + rlo] = h0;          g_obl[base + rlo] = __float2bfloat16(x0 - __bfloat162float(h0));
        g_obh[base + LL + rlo] = h1;     g_obl[base + LL + rlo] = __float2bfloat16(x1 - __bfloat162float(h1));
        g_obh[base + rlo + 8] = h2;      g_obl[base + rlo + 8] = __float2bfloat16(x2 - __bfloat162float(h2));
        g_obh[base + LL + rlo + 8] = h3; g_obl[base + LL + rlo + 8] = __float2bfloat16(x3 - __bfloat162float(h3));
    }
}

// ============ stream/event infra (created once, pre-baseline, leaked) ============
struct StreamInit {
    cudaStream_t s1;
    cudaEvent_t e0, ekv0, ekv1, edone;
    StreamInit() {
        cudaStreamCreateWithFlags(&s1, cudaStreamNonBlocking);
        cudaEventCreateWithFlags(&e0, cudaEventDisableTiming);
        cudaEventCreateWithFlags(&ekv0, cudaEventDisableTiming);
        cudaEventCreateWithFlags(&ekv1, cudaEventDisableTiming);
        cudaEventCreateWithFlags(&edone, cudaEventDisableTiming);
    }
};
static StreamInit g_si;

// ============ launch: half-pipelined, tensor work serialized on s1 ============
extern "C" void kernel_launch(void* const* d_in, const int* in_sizes, int n_in,
                              void* d_out, int out_size) {
    const float* q   = (const float*)d_in[0];
    const float* key = (const float*)d_in[1];
    const float* val = (const float*)d_in[2];
    const int*   ri  = (const int*)d_in[3];
    const float* Wi  = (const float*)d_in[4];
    const float* bi  = (const float*)d_in[5];
    const float* Wo  = (const float*)d_in[6];
    const float* bo  = (const float*)d_in[7];
    float* out = (float*)d_out;

    cudaFuncSetAttribute(k_kvproj, cudaFuncAttributeMaxDynamicSharedMemorySize, KV_SMEM);
    cudaFuncSetAttribute(k_attn_mma, cudaFuncAttributeMaxDynamicSharedMemorySize, ATTN_SMEM_B);
    cudaFuncSetAttribute(k_gemm, cudaFuncAttributeMaxDynamicSharedMemorySize, GEMM_SMEM);

    // origin stream (fma chain): weight prep + gather
    k_wt<<<1024, 256>>>(Wi, Wo);
    k_gatherQ<<<dim3(8, BB), 256>>>(q, ri);
    cudaEventRecord(g_si.e0, 0);

    // tensor stream s1: full Q projection overlapping the selection chain
    cudaStreamWaitEvent(g_si.s1, g_si.e0, 0);
    k_gemm<<<dim3(32, 2, BB), 256, GEMM_SMEM, g_si.s1>>>(q, out, bi, 0, SCALEF, 0);

    // --- half 0 (batches 0-3) selection on origin stream ---
    k_dist<<<dim3(128, 4), 256>>>(key, 0);
    k_topk1<<<dim3(8, 4), 512>>>(0);
    k_topk2<<<4, 1024>>>(0);
    k_kvproj<<<dim3(4, 4, 4), 256, KV_SMEM>>>(key, val, bi, 0);
    cudaEventRecord(g_si.ekv0, 0);

    // --- half 1 (batches 4-7) selection on origin stream (overlaps attn(0) on s1) ---
    k_dist<<<dim3(128, 4), 256>>>(key, 4);
    k_topk1<<<dim3(8, 4), 512>>>(4);
    k_topk2<<<4, 1024>>>(4);
    k_kvproj<<<dim3(4, 4, 4), 256, KV_SMEM>>>(key, val, bi, 4);
    cudaEventRecord(g_si.ekv1, 0);

    // tensor stream s1: attn + oproj per half, in program order
    cudaStreamWaitEvent(g_si.s1, g_si.ekv0, 0);
    k_attn_mma<<<dim3(32, HH, 4), 256, ATTN_SMEM_B, g_si.s1>>>(0);
    k_gemm<<<dim3(32, 2, 4), 256, GEMM_SMEM, g_si.s1>>>(q, out, bo, 1, 1.0f, 0);
    cudaStreamWaitEvent(g_si.s1, g_si.ekv1, 0);
    k_attn_mma<<<dim3(32, HH, 4), 256, ATTN_SMEM_B, g_si.s1>>>(4);
    k_gemm<<<dim3(32, 2, 4), 256, GEMM_SMEM, g_si.s1>>>(q, out, bo, 1, 1.0f, 4);

    // join
    cudaEventRecord(g_si.edone, g_si.s1);
    cudaStreamWaitEvent(0, g_si.edone, 0);
}

// round 15
// speedup vs baseline: 1.2985x; 1.2985x over previous
#include <cuda_runtime.h>
#include <cuda_bf16.h>
#include <cstdint>

// Shapes fixed by the dataset
#define BB 8
#define EE 256
#define LL 4096
#define SS 256          // top_k
#define HH 8
#define SCALEF 0.17677669529663687f   // 1/sqrt(32)

typedef unsigned long long ull;

// ---------------- device scratch ----------------
__device__ float g_nQs[BB * EE * SS];          // negated gathered queries [b][e][s]
__device__ float g_mind[BB * LL];              // min L1 distance per key pos
__device__ ull   g_cand[BB * 2048];            // per-chunk top-256 candidates
__device__ int   g_sel[BB * SS];               // selected indices
__device__ float g_WT[4 * EE * EE];            // transposed weights [m][ei][eo] (kvproj)
__device__ __nv_bfloat16 g_Wqh[EE * EE];       // Wq bf16 hi [eo][ei]
__device__ __nv_bfloat16 g_Wql[EE * EE];       // Wq bf16 lo
__device__ __nv_bfloat16 g_Woh[EE * EE];       // Wo bf16 hi [eo][ei]
__device__ __nv_bfloat16 g_Wol[EE * EE];       // Wo bf16 lo
__device__ __nv_bfloat16 g_qbh[(size_t)BB * EE * LL];  // projected Q bf16 hi [b][e][l]
__device__ __nv_bfloat16 g_qbl[(size_t)BB * EE * LL];  // projected Q bf16 lo
__device__ __nv_bfloat16 g_kbh[BB * SS * EE];  // projected K bf16 hi [b][j][e]
__device__ __nv_bfloat16 g_kbl[BB * SS * EE];
__device__ __nv_bfloat16 g_vbh[BB * SS * EE];  // projected V bf16 hi [b][j][e]
__device__ __nv_bfloat16 g_vbl[BB * SS * EE];
__device__ __nv_bfloat16 g_obh[(size_t)BB * EE * LL];  // attn out bf16 hi [b][e][l]
__device__ __nv_bfloat16 g_obl[(size_t)BB * EE * LL];

// ---------------- packed f32x2 helpers ----------------
__device__ __forceinline__ ull pk2(float lo, float hi) {
    ull r; asm("mov.b64 %0, {%1,%2};" : "=l"(r) : "f"(lo), "f"(hi)); return r;
}
__device__ __forceinline__ ull fadd2(ull a, ull b) {
    ull d; asm("add.rn.f32x2 %0, %1, %2;" : "=l"(d) : "l"(a), "l"(b)); return d;
}
__device__ __forceinline__ float2 upk2(ull v) {
    float2 r; asm("mov.b64 {%0,%1}, %2;" : "=f"(r.x), "=f"(r.y) : "l"(v)); return r;
}

// ---------------- warp MMA helpers ----------------
__device__ __forceinline__ uint32_t smem_u32(const void* p) {
    uint32_t a;
    asm("{ .reg .u64 t; cvta.to.shared.u64 t, %1; cvt.u32.u64 %0, t; }" : "=r"(a) : "l"(p));
    return a;
}
__device__ __forceinline__ uint32_t pkbf2(float lo, float hi) {
    uint32_t r; asm("cvt.rn.bf16x2.f32 %0, %1, %2;" : "=r"(r) : "f"(hi), "f"(lo)); return r;
}
__device__ __forceinline__ float lo16f(uint32_t u) { return __uint_as_float(u << 16); }
__device__ __forceinline__ float hi16f(uint32_t u) { return __uint_as_float(u & 0xFFFF0000u); }

__device__ __forceinline__ void ldmx4(uint32_t& r0, uint32_t& r1, uint32_t& r2, uint32_t& r3,
                                      uint32_t addr) {
    asm volatile("ldmatrix.sync.aligned.m8n8.x4.shared.b16 {%0,%1,%2,%3}, [%4];"
                 : "=r"(r0), "=r"(r1), "=r"(r2), "=r"(r3) : "r"(addr));
}
__device__ __forceinline__ void ldmx4t(uint32_t& r0, uint32_t& r1, uint32_t& r2, uint32_t& r3,
                                       uint32_t addr) {
    asm volatile("ldmatrix.sync.aligned.m8n8.x4.trans.shared.b16 {%0,%1,%2,%3}, [%4];"
                 : "=r"(r0), "=r"(r1), "=r"(r2), "=r"(r3) : "r"(addr));
}
__device__ __forceinline__ void mma16816(float* d, uint32_t a0, uint32_t a1, uint32_t a2,
                                         uint32_t a3, uint32_t b0, uint32_t b1) {
    asm volatile("mma.sync.aligned.m16n8k16.row.col.f32.bf16.bf16.f32 "
                 "{%0,%1,%2,%3}, {%4,%5,%6,%7}, {%8,%9}, {%0,%1,%2,%3};"
                 : "+f"(d[0]), "+f"(d[1]), "+f"(d[2]), "+f"(d[3])
                 : "r"(a0), "r"(a1), "r"(a2), "r"(a3), "r"(b0), "r"(b1));
}

// ============ kernel 0: weight prep ============
__global__ __launch_bounds__(256) void k_wt(const float* __restrict__ Wi,
                                            const float* __restrict__ Wo) {
    int lin = blockIdx.x * 256 + threadIdx.x;
    int m = lin >> 16;
    int r = lin & 0xFFFF;
    int ei = r >> 8, eo = r & 255;
    float v = (m < 3) ? Wi[(m * EE + eo) * EE + ei] : Wo[eo * EE + ei];
    g_WT[lin] = v;
    if (m == 0) {
        __nv_bfloat16 hi = __float2bfloat16(v);
        g_Wqh[eo * EE + ei] = hi;
        g_Wql[eo * EE + ei] = __float2bfloat16(v - __bfloat162float(hi));
    } else if (m == 3) {
        __nv_bfloat16 hi = __float2bfloat16(v);
        g_Woh[eo * EE + ei] = hi;
        g_Wol[eo * EE + ei] = __float2bfloat16(v - __bfloat162float(hi));
    }
}

// ============ kernel 1: gather negated subset queries ============
__global__ __launch_bounds__(256) void k_gatherQ(const float* __restrict__ q,
                                                 const int* __restrict__ rind) {
    __shared__ int sidx[SS];
    int b = blockIdx.y, t = threadIdx.x;
    sidx[t] = rind[b * SS + t];
    __syncthreads();
    int e0 = blockIdx.x * 32;
    const float* qb = q + (size_t)b * EE * LL;
    int idx = sidx[t];
    float* dst = g_nQs + ((size_t)b * EE + e0) * SS + t;
    const float* srcp = qb + (size_t)e0 * LL + idx;
#pragma unroll 8
    for (int e = 0; e < 32; e++) dst[e * SS] = -srcp[(size_t)e * LL];
}

// ============ kernel 2: min-over-subset L1 distances ============
__global__ __launch_bounds__(256, 4) void k_dist(const float* __restrict__ keys) {
    __shared__ float Kt[16 * 32];
    __shared__ float Qs[16 * SS];
    int t = threadIdx.x, tx = t & 15, ty = t >> 4;
    int b = blockIdx.y, lb = blockIdx.x * 32;
    const float* kb = keys + (size_t)b * EE * LL;
    const float* qb = g_nQs + (size_t)b * EE * SS;

    ull acc[2][8];
#pragma unroll
    for (int i = 0; i < 2; i++)
#pragma unroll
        for (int p = 0; p < 8; p++) acc[i][p] = 0ull;

    for (int e0 = 0; e0 < EE; e0 += 16) {
        {
            int r = t >> 4, c2 = (t & 15) * 2;
            *(float2*)&Kt[r * 32 + c2] = *(const float2*)&kb[(size_t)(e0 + r) * LL + lb + c2];
        }
#pragma unroll
        for (int v = 0; v < 4; v++) {
            int lin4 = v * 256 + t;
            int r = lin4 >> 6, c4 = (lin4 & 63) * 4;
            *(float4*)&Qs[r * SS + c4] = *(const float4*)&qb[(size_t)(e0 + r) * SS + c4];
        }
        __syncthreads();
#pragma unroll
        for (int ec = 0; ec < 16; ec++) {
            float kv0 = Kt[ec * 32 + ty * 2];
            float kv1 = Kt[ec * 32 + ty * 2 + 1];
            ull kk0 = pk2(kv0, kv0);
            ull kk1 = pk2(kv1, kv1);
            const ull* qp = (const ull*)&Qs[ec * SS];
#pragma unroll
            for (int p = 0; p < 8; p++) {
                ull q2 = qp[tx + p * 16];
                ull d0 = fadd2(kk0, q2);
                d0 &= 0x7FFFFFFF7FFFFFFFULL;
                acc[0][p] = fadd2(acc[0][p], d0);
                ull d1 = fadd2(kk1, q2);
                d1 &= 0x7FFFFFFF7FFFFFFFULL;
                acc[1][p] = fadd2(acc[1][p], d1);
            }
        }
        __syncthreads();
    }
#pragma unroll
    for (int i = 0; i < 2; i++) {
        float m = 3.0e38f;
#pragma unroll
        for (int p = 0; p < 8; p++) {
            float2 f = upk2(acc[i][p]);
            m = fminf(m, fminf(f.x, f.y));
        }
#pragma unroll
        for (int o = 8; o >= 1; o >>= 1)
            m = fminf(m, __shfl_xor_sync(0xffffffffu, m, o));
        if (tx == 0) g_mind[b * LL + lb + ty * 2 + i] = m;
    }
}

// ============ kernel 3a: per-chunk bitonic 512 -> keep 256 smallest ============
__global__ __launch_bounds__(512) void k_topk1() {
    __shared__ ull keyv[512];
    int t = threadIdx.x, chunk = blockIdx.x, b = blockIdx.y;
    int base = chunk * 512;
    {
        unsigned int bits = __float_as_uint(g_mind[b * LL + base + t]);
        keyv[t] = ((ull)bits << 32) | (unsigned int)(base + t);
    }
    __syncthreads();
    for (int k = 2; k <= 512; k <<= 1) {
        for (int j = k >> 1; j > 0; j >>= 1) {
            int ixj = t ^ j;
            if (ixj > t) {
                ull a = keyv[t], c = keyv[ixj];
                bool up = ((t & k) == 0);
                if ((a > c) == up) { keyv[t] = c; keyv[ixj] = a; }
            }
            __syncthreads();
        }
    }
    if (t < 256) g_cand[b * 2048 + chunk * 256 + t] = keyv[t];
}

// ============ kernel 3b: merge 8x256 candidates -> 256 smallest ============
__global__ __launch_bounds__(1024) void k_topk2() {
    __shared__ ull keyv[2048];
    int t = threadIdx.x, b = blockIdx.x;
    keyv[t] = g_cand[b * 2048 + t];
    keyv[t + 1024] = g_cand[b * 2048 + t + 1024];
    __syncthreads();
    for (int k = 2; k <= 2048; k <<= 1) {
        for (int j = k >> 1; j > 0; j >>= 1) {
            for (int i = t; i < 2048; i += 1024) {
                int ixj = i ^ j;
                if (ixj > i) {
                    ull a = keyv[i], c = keyv[ixj];
                    bool up = ((i & k) == 0);
                    if ((a > c) == up) { keyv[i] = c; keyv[ixj] = a; }
                }
            }
            __syncthreads();
        }
    }
    if (t < SS) g_sel[b * SS + t] = (int)(keyv[t] & 0xFFFFFFFFULL);
}

// ============ kernel 4: gather selected K/V, project, emit bf16 hi/lo [b][j][e] ============
#define KV_SMEM ((64 * 264 + 16 * 128) * 4)
__global__ __launch_bounds__(256) void k_kvproj(const float* __restrict__ keys,
                                                const float* __restrict__ values,
                                                const float* __restrict__ bias_in) {
    extern __shared__ float sm[];
    float* skv = sm;
    float* Wt  = sm + 64 * 264;
    __shared__ int sidx[64];
    int t = threadIdx.x, b = blockIdx.y, jb = blockIdx.x * 64;
    int zc = blockIdx.z, ph = zc >> 1, half = zc & 1;
    if (t < 64) sidx[t] = g_sel[b * SS + jb + t];
    __syncthreads();
    int txE = t & 15, tyJ = t >> 4;

    const float* src = (ph ? values : keys) + (size_t)b * EE * LL;
#pragma unroll 8
    for (int j = 0; j < 64; j++)
        skv[j * 264 + t] = src[(size_t)t * LL + sidx[j]];
    __syncthreads();

    const float* WTm = g_WT + (size_t)(ph + 1) * EE * EE + half * 128;
    float acc[4][8];
#pragma unroll
    for (int i = 0; i < 4; i++)
#pragma unroll
        for (int c = 0; c < 8; c++) acc[i][c] = 0.f;

    for (int ei0 = 0; ei0 < EE; ei0 += 16) {
#pragma unroll
        for (int v = 0; v < 2; v++) {
            int lin4 = v * 256 + t;
            int r = lin4 >> 5, c4 = (lin4 & 31) * 4;
            *(float4*)&Wt[r * 128 + c4] = *(const float4*)&WTm[(size_t)(ei0 + r) * EE + c4];
        }
        __syncthreads();
#pragma unroll
        for (int ec = 0; ec < 16; ec++) {
            float a[4];
#pragma unroll
            for (int i = 0; i < 4; i++) a[i] = skv[(tyJ * 4 + i) * 264 + ei0 + ec];
#pragma unroll
            for (int c = 0; c < 8; c++) {
                float w = Wt[ec * 128 + c * 16 + txE];
#pragma unroll
                for (int i = 0; i < 4; i++) acc[i][c] += a[i] * w;
            }
        }
        __syncthreads();
    }
    __nv_bfloat16* dh = ph ? g_vbh : g_kbh;
    __nv_bfloat16* dl = ph ? g_vbl : g_kbl;
    const float* bp = bias_in + (ph ? 2 * EE : EE) + half * 128;
#pragma unroll
    for (int c = 0; c < 8; c++) {
        int eo = c * 16 + txE;
        float bb = bp[eo];
#pragma unroll
        for (int i = 0; i < 4; i++) {
            float x = acc[i][c] + bb;
            __nv_bfloat16 hi = __float2bfloat16(x);
            size_t o = ((size_t)b * SS + jb + tyJ * 4 + i) * EE + half * 128 + eo;
            dh[o] = hi;
            dl[o] = __float2bfloat16(x - __bfloat162float(hi));
        }
    }
}

// ============ kernel 5: HMMA GEMM  C[eo][l] = W[eo][ei] @ X[ei][l] ============
#define WHI_OFF 0
#define WLO_OFF 18432
#define BHI_OFF 36864
#define BLO_OFF 54272
#define GEMM_SMEM 71680
#define WP 72
#define BP 136

__global__ __launch_bounds__(256, 2) void k_gemm(const float* __restrict__ Bext,
                                                 float* __restrict__ OutExt,
                                                 const float* __restrict__ bias,
                                                 int which, float scale) {
    extern __shared__ char smc[];
    uint32_t sb = smem_u32(smc);
    __nv_bfloat16* Ws_hi = (__nv_bfloat16*)(smc + WHI_OFF);
    __nv_bfloat16* Ws_lo = (__nv_bfloat16*)(smc + WLO_OFF);
    __nv_bfloat16* Bs_hi = (__nv_bfloat16*)(smc + BHI_OFF);
    __nv_bfloat16* Bs_lo = (__nv_bfloat16*)(smc + BLO_OFF);

    int t = threadIdx.x, w = t >> 5, lane = t & 31;
    int lb = blockIdx.x * 128, eo0 = blockIdx.y * 128, b = blockIdx.z;

    const __nv_bfloat16* Whi = which ? g_Woh : g_Wqh;
    const __nv_bfloat16* Wlo = which ? g_Wol : g_Wql;

    float o[16][4];
#pragma unroll
    for (int j = 0; j < 16; j++)
#pragma unroll
        for (int i = 0; i < 4; i++) o[j][i] = 0.f;

    for (int ei0 = 0; ei0 < EE; ei0 += 64) {
        for (int idx = t; idx < 2048; idx += 256) {
            int c4 = (idx & 15) * 4, r = idx >> 4;
            size_t g = (size_t)(eo0 + r) * EE + ei0 + c4;
            *(ull*)&Ws_hi[r * WP + c4] = *(const ull*)&Whi[g];
            *(ull*)&Ws_lo[r * WP + c4] = *(const ull*)&Wlo[g];
        }
        if (which == 0) {
            for (int idx = t; idx < 2048; idx += 256) {
                int l4 = (idx & 31) * 4, e = idx >> 5;
                float4 x = *(const float4*)&Bext[((size_t)b * EE + ei0 + e) * LL + lb + l4];
                uint32_t uh0 = pkbf2(x.x, x.y), uh1 = pkbf2(x.z, x.w);
                uint32_t ul0 = pkbf2(x.x - lo16f(uh0), x.y - hi16f(uh0));
                uint32_t ul1 = pkbf2(x.z - lo16f(uh1), x.w - hi16f(uh1));
                *(ull*)&Bs_hi[e * BP + l4] = (ull)uh0 | ((ull)uh1 << 32);
                *(ull*)&Bs_lo[e * BP + l4] = (ull)ul0 | ((ull)ul1 << 32);
            }
        } else {
            for (int idx = t; idx < 2048; idx += 256) {
                int l4 = (idx & 31) * 4, e = idx >> 5;
                size_t g = ((size_t)b * EE + ei0 + e) * LL + lb + l4;
                *(ull*)&Bs_hi[e * BP + l4] = *(const ull*)&g_obh[g];
                *(ull*)&Bs_lo[e * BP + l4] = *(const ull*)&g_obl[g];
            }
        }
        __syncthreads();

        int arow = w * 16 + (lane & 7) + ((lane >> 3) & 1) * 8;
        int brow = (lane & 7) + ((lane >> 3) & 1) * 8;
        int bcol = (lane >> 4) * 8;
#pragma unroll
        for (int ks = 0; ks < 4; ks++) {
            int acol = ks * 16 + (lane >> 4) * 8;
            uint32_t ah0, ah1, ah2, ah3, al0, al1, al2, al3;
            ldmx4(ah0, ah1, ah2, ah3, sb + WHI_OFF + (arow * WP + acol) * 2);
            ldmx4(al0, al1, al2, al3, sb + WLO_OFF + (arow * WP + acol) * 2);
            uint32_t roff = ((ks * 16 + brow) * BP + bcol) * 2;
#pragma unroll
            for (int nt = 0; nt < 8; nt++) {
                uint32_t coff = roff + nt * 32;
                uint32_t bh0, bh1, bh2, bh3, bl0, bl1, bl2, bl3;
                ldmx4t(bh0, bh1, bh2, bh3, sb + BHI_OFF + coff);
                ldmx4t(bl0, bl1, bl2, bl3, sb + BLO_OFF + coff);
                mma16816(o[nt * 2],     ah0, ah1, ah2, ah3, bh0, bh1);
                mma16816(o[nt * 2 + 1], ah0, ah1, ah2, ah3, bh2, bh3);
                mma16816(o[nt * 2],     ah0, ah1, ah2, ah3, bl0, bl1);
                mma16816(o[nt * 2 + 1], ah0, ah1, ah2, ah3, bl2, bl3);
                mma16816(o[nt * 2],     al0, al1, al2, al3, bh0, bh1);
                mma16816(o[nt * 2 + 1], al0, al1, al2, al3, bh2, bh3);
            }
        }
        __syncthreads();
    }

    int r0 = eo0 + w * 16 + (lane >> 2);
    float b0v = bias[r0], b1v = bias[r0 + 8];
    size_t base0 = ((size_t)b * EE + r0) * LL + lb;
    size_t base1 = base0 + 8 * LL;
    if (which == 1) {
#pragma unroll
        for (int j = 0; j < 16; j++) {
            int lc = j * 8 + (lane & 3) * 2;
            *(float2*)&OutExt[base0 + lc] = make_float2(o[j][0] + b0v, o[j][1] + b0v);
            *(float2*)&OutExt[base1 + lc] = make_float2(o[j][2] + b1v, o[j][3] + b1v);
        }
    } else {
#pragma unroll
        for (int j = 0; j < 16; j++) {
            int lc = j * 8 + (lane & 3) * 2;
            float x0 = (o[j][0] + b0v) * scale, x1 = (o[j][1] + b0v) * scale;
            float x2 = (o[j][2] + b1v) * scale, x3 = (o[j][3] + b1v) * scale;
            uint32_t h0 = pkbf2(x0, x1);
            uint32_t l0 = pkbf2(x0 - lo16f(h0), x1 - hi16f(h0));
            uint32_t h1 = pkbf2(x2, x3);
            uint32_t l1 = pkbf2(x2 - lo16f(h1), x3 - hi16f(h1));
            *(uint32_t*)&g_qbh[base0 + lc] = h0;
            *(uint32_t*)&g_qbl[base0 + lc] = l0;
            *(uint32_t*)&g_qbh[base1 + lc] = h1;
            *(uint32_t*)&g_qbl[base1 + lc] = l1;
        }
    }
}

// ============ kernel 6: attention, online-softmax (2 j-tiles), 2 blocks/SM ============
#define PITCH 40
#define QHI 0
#define QLO 10240
#define KHI 20480
#define KLO 40960
#define VHI 61440
#define VLO 81920
#define ATTN_SMEM_B 102400

__global__ __launch_bounds__(256, 2) void k_attn_mma() {
    extern __shared__ char smc[];
    int t = threadIdx.x, w = t >> 5, lane = t & 31;
    int b = blockIdx.z, h = blockIdx.y, lb = blockIdx.x * 128;
    uint32_t sb = smem_u32(smc);

    // ---- Q tile (128 l x 32 d) from g_qbh/g_qbl [b][e][l]
    for (int idx = t; idx < 2048; idx += 256) {
        int d = idx >> 6, lp = idx & 63;
        int l = lp * 2;
        size_t g = ((size_t)b * EE + h * 32 + d) * LL + lb + l;
        uint32_t uh = *(const uint32_t*)&g_qbh[g];
        uint32_t ul = *(const uint32_t*)&g_qbl[g];
        *(uint16_t*)(smc + QHI + (l * PITCH + d) * 2) = (uint16_t)uh;
        *(uint16_t*)(smc + QHI + ((l + 1) * PITCH + d) * 2) = (uint16_t)(uh >> 16);
        *(uint16_t*)(smc + QLO + (l * PITCH + d) * 2) = (uint16_t)ul;
        *(uint16_t*)(smc + QLO + ((l + 1) * PITCH + d) * 2) = (uint16_t)(ul >> 16);
    }
    // ---- K/V tiles (256 j x 32 d)
    for (int idx = t; idx < 2048; idx += 256) {
        int j = idx >> 3, d4 = (idx & 7) * 4;
        size_t g = ((size_t)b * SS + j) * EE + h * 32 + d4;
        *(ull*)(smc + KHI + (j * PITCH + d4) * 2) = *(const ull*)&g_kbh[g];
        *(ull*)(smc + KLO + (j * PITCH + d4) * 2) = *(const ull*)&g_kbl[g];
        *(ull*)(smc + VHI + (j * PITCH + d4) * 2) = *(const ull*)&g_vbh[g];
        *(ull*)(smc + VLO + (j * PITCH + d4) * 2) = *(const ull*)&g_vbl[g];
    }
    __syncthreads();

    int m0 = w * 16;
    int arow = m0 + (lane & 7) + ((lane >> 3) & 1) * 8;
    int brow = (lane & 7) + ((lane >> 4) & 1) * 8;
    int bcolb = ((lane >> 3) & 1) * 8;
    int vrow = (lane & 7) + ((lane >> 3) & 1) * 8;
    int vcolsel = (lane >> 4) * 8;

    const uint32_t qb2[2] = { sb + QHI, sb + QLO };
    const uint32_t kb2[2] = { sb + KHI, sb + KLO };
    const int TERM_A[3] = { 0, 0, 1 };
    const int TERM_B[3] = { 0, 1, 0 };

    float mr0 = -3.0e38f, mr1 = -3.0e38f, sr0 = 0.f, sr1 = 0.f;
    float o[4][4];
#pragma unroll
    for (int nt = 0; nt < 4; nt++)
#pragma unroll
        for (int i = 0; i < 4; i++) o[nt][i] = 0.f;

#pragma unroll
    for (int jt = 0; jt < 2; jt++) {
        // ---- scores for this j-tile (128 wide), 3-term bf16 split
        float sc[16][4];
#pragma unroll
        for (int nt = 0; nt < 16; nt++)
#pragma unroll
            for (int i = 0; i < 4; i++) sc[nt][i] = 0.f;

#pragma unroll
        for (int tm = 0; tm < 3; tm++) {
            uint32_t qb = qb2[TERM_A[tm]], kb = kb2[TERM_B[tm]];
#pragma unroll
            for (int kd = 0; kd < 2; kd++) {
                int acol = kd * 16 + (lane >> 4) * 8;
                uint32_t a0, a1, a2, a3;
                ldmx4(a0, a1, a2, a3, qb + (arow * PITCH + acol) * 2);
                int bcol = kd * 16 + bcolb;
#pragma unroll
                for (int jp = 0; jp < 8; jp++) {
                    int j0 = jt * 128 + jp * 16;
                    uint32_t b0, b1, b2, b3;
                    ldmx4(b0, b1, b2, b3, kb + ((j0 + brow) * PITCH + bcol) * 2);
                    mma16816(sc[jp * 2],     a0, a1, a2, a3, b0, b1);
                    mma16816(sc[jp * 2 + 1], a0, a1, a2, a3, b2, b3);
                }
            }
        }

        // ---- online softmax update (rows rlo = m0+lane/4 and rhi = rlo+8)
        float tmx0 = -3.0e38f, tmx1 = -3.0e38f;
#pragma unroll
        for (int nt = 0; nt < 16; nt++) {
            tmx0 = fmaxf(tmx0, fmaxf(sc[nt][0], sc[nt][1]));
            tmx1 = fmaxf(tmx1, fmaxf(sc[nt][2], sc[nt][3]));
        }
        tmx0 = fmaxf(tmx0, __shfl_xor_sync(0xffffffffu, tmx0, 1));
        tmx0 = fmaxf(tmx0, __shfl_xor_sync(0xffffffffu, tmx0, 2));
        tmx1 = fmaxf(tmx1, __shfl_xor_sync(0xffffffffu, tmx1, 1));
        tmx1 = fmaxf(tmx1, __shfl_xor_sync(0xffffffffu, tmx1, 2));
        float nm0 = fmaxf(mr0, tmx0), nm1 = fmaxf(mr1, tmx1);
        float f0 = __expf(mr0 - nm0), f1 = __expf(mr1 - nm1);
#pragma unroll
        for (int nt = 0; nt < 4; nt++) {
            o[nt][0] *= f0; o[nt][1] *= f0;
            o[nt][2] *= f1; o[nt][3] *= f1;
        }
        sr0 *= f0; sr1 *= f1;
        mr0 = nm0; mr1 = nm1;

        float ts0 = 0.f, ts1 = 0.f;
#pragma unroll
        for (int nt = 0; nt < 16; nt++) {
            sc[nt][0] = __expf(sc[nt][0] - nm0); ts0 += sc[nt][0];
            sc[nt][1] = __expf(sc[nt][1] - nm0); ts0 += sc[nt][1];
            sc[nt][2] = __expf(sc[nt][2] - nm1); ts1 += sc[nt][2];
            sc[nt][3] = __expf(sc[nt][3] - nm1); ts1 += sc[nt][3];
        }
        ts0 += __shfl_xor_sync(0xffffffffu, ts0, 1);
        ts0 += __shfl_xor_sync(0xffffffffu, ts0, 2);
        ts1 += __shfl_xor_sync(0xffffffffu, ts1, 1);
        ts1 += __shfl_xor_sync(0xffffffffu, ts1, 2);
        sr0 += ts0; sr1 += ts1;

        // ---- PV for this tile (unnormalized P, basis nm)
#pragma unroll
        for (int kt = 0; kt < 8; kt++) {
            uint32_t ah0 = pkbf2(sc[2 * kt][0], sc[2 * kt][1]);
            uint32_t ah1 = pkbf2(sc[2 * kt][2], sc[2 * kt][3]);
            uint32_t ah2 = pkbf2(sc[2 * kt + 1][0], sc[2 * kt + 1][1]);
            uint32_t ah3 = pkbf2(sc[2 * kt + 1][2], sc[2 * kt + 1][3]);
            uint32_t al0 = pkbf2(sc[2 * kt][0] - lo16f(ah0), sc[2 * kt][1] - hi16f(ah0));
            uint32_t al1 = pkbf2(sc[2 * kt][2] - lo16f(ah1), sc[2 * kt][3] - hi16f(ah1));
            uint32_t al2 = pkbf2(sc[2 * kt + 1][0] - lo16f(ah2), sc[2 * kt + 1][1] - hi16f(ah2));
            uint32_t al3 = pkbf2(sc[2 * kt + 1][2] - lo16f(ah3), sc[2 * kt + 1][3] - hi16f(ah3));
            uint32_t rbase = ((jt * 128 + kt * 16 + vrow) * PITCH) * 2;
#pragma unroll
            for (int np = 0; np < 2; np++) {
                uint32_t off = rbase + (np * 16 + vcolsel) * 2;
                uint32_t h0, h1, h2, h3, l0, l1, l2, l3;
                ldmx4t(h0, h1, h2, h3, sb + VHI + off);
                ldmx4t(l0, l1, l2, l3, sb + VLO + off);
                mma16816(o[np * 2],     ah0, ah1, ah2, ah3, h0, h1);
                mma16816(o[np * 2 + 1], ah0, ah1, ah2, ah3, h2, h3);
                mma16816(o[np * 2],     ah0, ah1, ah2, ah3, l0, l1);
                mma16816(o[np * 2 + 1], ah0, ah1, ah2, ah3, l2, l3);
                mma16816(o[np * 2],     al0, al1, al2, al3, h0, h1);
                mma16816(o[np * 2 + 1], al0, al1, al2, al3, h2, h3);
            }
        }
    }

    // ---- epilogue: normalize and store bf16 hi/lo
    float ri0 = 1.0f / sr0, ri1 = 1.0f / sr1;
    int rlo = m0 + (lane >> 2);
#pragma unroll
    for (int nt = 0; nt < 4; nt++) {
        int e = h * 32 + nt * 8 + (lane & 3) * 2;
        size_t base = ((size_t)b * EE + e) * LL + lb;
        float x0 = o[nt][0] * ri0, x1 = o[nt][1] * ri0;
        float x2 = o[nt][2] * ri1, x3 = o[nt][3] * ri1;
        __nv_bfloat16 h0 = __float2bfloat16(x0);
        __nv_bfloat16 h1 = __float2bfloat16(x1);
        __nv_bfloat16 h2 = __float2bfloat16(x2);
        __nv_bfloat16 h3 = __float2bfloat16(x3);
        g_obh[base + rlo] = h0;          g_obl[base + rlo] = __float2bfloat16(x0 - __bfloat162float(h0));
        g_obh[base + LL + rlo] = h1;     g_obl[base + LL + rlo] = __float2bfloat16(x1 - __bfloat162float(h1));
        g_obh[base + rlo + 8] = h2;      g_obl[base + rlo + 8] = __float2bfloat16(x2 - __bfloat162float(h2));
        g_obh[base + LL + rlo + 8] = h3; g_obl[base + LL + rlo + 8] = __float2bfloat16(x3 - __bfloat162float(h3));
    }
}

// ============ stream/event infra (created once, pre-baseline, leaked) ============
struct StreamInit {
    cudaStream_t s1;
    cudaEvent_t e0, e2;
    StreamInit() {
        cudaStreamCreateWithFlags(&s1, cudaStreamNonBlocking);
        cudaEventCreateWithFlags(&e0, cudaEventDisableTiming);
        cudaEventCreateWithFlags(&e2, cudaEventDisableTiming);
    }
};
static StreamInit g_si;

// ============ launch: R13 topology (best known) ============
extern "C" void kernel_launch(void* const* d_in, const int* in_sizes, int n_in,
                              void* d_out, int out_size) {
    const float* q   = (const float*)d_in[0];
    const float* key = (const float*)d_in[1];
    const float* val = (const float*)d_in[2];
    const int*   ri  = (const int*)d_in[3];
    const float* Wi  = (const float*)d_in[4];
    const float* bi  = (const float*)d_in[5];
    const float* Wo  = (const float*)d_in[6];
    const float* bo  = (const float*)d_in[7];
    float* out = (float*)d_out;

    cudaFuncSetAttribute(k_kvproj, cudaFuncAttributeMaxDynamicSharedMemorySize, KV_SMEM);
    cudaFuncSetAttribute(k_attn_mma, cudaFuncAttributeMaxDynamicSharedMemorySize, ATTN_SMEM_B);
    cudaFuncSetAttribute(k_gemm, cudaFuncAttributeMaxDynamicSharedMemorySize, GEMM_SMEM);

    // main stream: weight prep, then dist -> topk -> kvproj chain
    k_wt<<<1024, 256>>>(Wi, Wo);
    cudaEventRecord(g_si.e0, 0);
    // side stream: Q projection (depends only on k_wt + raw q)
    cudaStreamWaitEvent(g_si.s1, g_si.e0, 0);
    k_gemm<<<dim3(32, 2, BB), 256, GEMM_SMEM, g_si.s1>>>(q, out, bi, 0, SCALEF);
    cudaEventRecord(g_si.e2, g_si.s1);

    k_gatherQ<<<dim3(8, BB), 256>>>(q, ri);
    k_dist<<<dim3(128, BB), 256>>>(key);
    k_topk1<<<dim3(8, BB), 512>>>();
    k_topk2<<<BB, 1024>>>();
    k_kvproj<<<dim3(4, BB, 4), 256, KV_SMEM>>>(key, val, bi);

    // join: attention needs both Q projection and K/V projection
    cudaStreamWaitEvent(0, g_si.e2, 0);
    k_attn_mma<<<dim3(32, HH, BB), 256, ATTN_SMEM_B>>>();
    k_gemm<<<dim3(32, 2, BB), 256, GEMM_SMEM>>>(q, out, bo, 1, 1.0f);
}